// round 2
// baseline (speedup 1.0000x reference)
#include <cuda_runtime.h>
#include <cstdint>

// S3FD anchor assignment, fused single-pass.
//   K1: per-anchor IoU vs all GT (GT boxes in smem), max/argmax -> stage-1 assign,
//       per-GT top-3 maintained via lock-free atomicMax cascade (smem, then global).
//   K2: per-GT claims (k=0 always; k=1,2 if "low" && val>0.1) -> atomicMax scatter into forced[].
//   K3: assign = forced >= 0 ? forced : assign.
// OUTPUT IS float32 (harness __output__ dtype): values are small ints stored as floats.
// All IoU arithmetic uses explicit round-to-nearest intrinsics to be bit-identical
// to the float32 reference regardless of compiler fast-math flags.

#define TPB 256
#define APT 4           // anchors per thread
#define MAXM 256        // >= number of GT boxes (200)
#define MAXN (1 << 20)  // >= number of anchors (500000)

__device__ unsigned long long g_top3[MAXM * 3];
__device__ int g_forced[MAXN];

// Lock-free top-3 insert: each slot is monotone non-decreasing under atomicMax;
// the displaced (smaller) value cascades to the next slot. Final state is the
// exact sorted top-3 of all inserted keys (keys are distinct: low bits = ~anchor_idx).
__device__ __forceinline__ void cascade_insert(unsigned long long* s, unsigned long long v) {
#pragma unroll
    for (int i = 0; i < 3; i++) {
        unsigned long long old = atomicMax(&s[i], v);
        v = old < v ? old : v;   // push the displaced minimum down
        if (v == 0ull) return;   // nothing real to push
    }
}

__global__ void __launch_bounds__(TPB) k1_assign(
    const float4* __restrict__ anc, const float4* __restrict__ gts,
    int n, int m, float* __restrict__ out, unsigned long long* __restrict__ gtop)
{
    __shared__ float4 sg[MAXM];
    __shared__ float sga[MAXM];
    __shared__ unsigned long long stop[MAXM * 3];

    const int tid = threadIdx.x;
    for (int i = tid; i < m; i += TPB) {
        float4 g = gts[i];
        sg[i] = g;
        sga[i] = __fmul_rn(__fsub_rn(g.z, g.x), __fsub_rn(g.w, g.y));
    }
    for (int i = tid; i < m * 3; i += TPB) stop[i] = 0ull;
    __syncthreads();

    const int base = blockIdx.x * (TPB * APT) + tid;
    float ax1[APT], ay1[APT], ax2[APT], ay2[APT], aar[APT], best[APT];
    int bidx[APT], idx[APT];
#pragma unroll
    for (int j = 0; j < APT; j++) {
        int i = base + j * TPB;
        idx[j] = i;
        float4 a = (i < n) ? anc[i] : make_float4(0.f, 0.f, 0.f, 0.f);
        ax1[j] = a.x; ay1[j] = a.y; ax2[j] = a.z; ay2[j] = a.w;
        aar[j] = __fmul_rn(__fsub_rn(a.z, a.x), __fsub_rn(a.w, a.y));
        best[j] = 0.f;   // all-zero row -> argmax 0, matching reference
        bidx[j] = 0;
    }

    // 32-bit view of the high (iou-bits) word of each 64-bit slot.
    // Slot values are monotone non-decreasing, so a stale 32-bit read is a
    // safe lower bound for the skip test (never skips a needed insert).
    const unsigned* stop_hi = (const unsigned*)stop;

    for (int g = 0; g < m; g++) {
        float4 G = sg[g];
        float ga = sga[g];
        unsigned min_hi = stop_hi[(g * 3 + 2) * 2 + 1];
#pragma unroll
        for (int j = 0; j < APT; j++) {
            float ltx = fmaxf(ax1[j], G.x), lty = fmaxf(ay1[j], G.y);
            float rbx = fminf(ax2[j], G.z), rby = fminf(ay2[j], G.w);
            float w = fmaxf(__fsub_rn(rbx, ltx), 0.f);
            float h = fmaxf(__fsub_rn(rby, lty), 0.f);
            float inter = __fmul_rn(w, h);
            if (inter > 0.f) {
                float denom = __fsub_rn(__fadd_rn(aar[j], ga), inter);
                float iou = __fdiv_rn(inter, denom);   // IEEE rn, matches reference
                if (iou > best[j]) { best[j] = iou; bidx[j] = g; }
                unsigned ib = __float_as_uint(iou);
                if (ib >= min_hi) {
                    // key orders by (iou, then lower anchor index first)
                    unsigned long long key =
                        ((unsigned long long)ib << 32) | (unsigned)(~(unsigned)idx[j]);
                    cascade_insert(&stop[g * 3], key);
                    min_hi = stop_hi[(g * 3 + 2) * 2 + 1];
                }
            }
        }
    }

#pragma unroll
    for (int j = 0; j < APT; j++) {
        if (idx[j] < n) {
            float a = -2.0f;
            if (best[j] < 0.3f) a = -1.0f;
            if (best[j] > 0.5f) a = (float)bidx[j];
            out[idx[j]] = a;
        }
    }

    // Merge this block's per-GT top-3 into the global cascade.
    __syncthreads();
    const unsigned* gtop_hi = (const unsigned*)gtop;
    for (int i = tid; i < m * 3; i += TPB) {
        unsigned long long v = stop[i];
        if (!v) continue;
        int g = i / 3;
        unsigned gm = gtop_hi[(g * 3 + 2) * 2 + 1];
        if ((unsigned)(v >> 32) >= gm) cascade_insert(&gtop[g * 3], v);
    }
}

__global__ void k2_claims(const unsigned long long* __restrict__ gtop, int m,
                          int* __restrict__ forced)
{
    int g = blockIdx.x * blockDim.x + threadIdx.x;
    if (g >= m) return;
    unsigned long long s0 = gtop[g * 3 + 0];
    unsigned long long s1 = gtop[g * 3 + 1];
    unsigned long long s2 = gtop[g * 3 + 2];
    float v0 = __uint_as_float((unsigned)(s0 >> 32));
    float v1 = __uint_as_float((unsigned)(s1 >> 32));
    float v2 = __uint_as_float((unsigned)(s2 >> 32));
    int npos = (v0 > 0.5f) + (v1 > 0.5f) + (v2 > 0.5f);
    bool low = npos < 3;
    // k==0 is ALWAYS claimed. If no anchor ever overlapped this gt (slot empty),
    // the reference's top_k of an all-zero row returns rank 0 -> anchor index 0.
    if (s0) atomicMax(&forced[(int)(~(unsigned)s0)], g);
    else    atomicMax(&forced[0], g);
    if (low) {
        if (s1 && v1 > 0.1f) atomicMax(&forced[(int)(~(unsigned)s1)], g);
        if (s2 && v2 > 0.1f) atomicMax(&forced[(int)(~(unsigned)s2)], g);
    }
}

__global__ void k3_merge(const int* __restrict__ forced, int n, float* __restrict__ out)
{
    int i = blockIdx.x * blockDim.x + threadIdx.x;
    if (i < n) {
        int f = forced[i];
        if (f >= 0) out[i] = (float)f;
    }
}

extern "C" void kernel_launch(void* const* d_in, const int* in_sizes, int n_in,
                              void* d_out, int out_size)
{
    const float4* anc = (const float4*)d_in[0];
    const float4* gts = (const float4*)d_in[1];
    int n = in_sizes[0] / 4;
    int m = in_sizes[1] / 4;
    float* out = (float*)d_out;

    void *ptop = nullptr, *pforced = nullptr;
    cudaGetSymbolAddress(&ptop, g_top3);
    cudaGetSymbolAddress(&pforced, g_forced);

    cudaMemsetAsync(ptop, 0, (size_t)m * 3 * sizeof(unsigned long long));
    cudaMemsetAsync(pforced, 0xFF, (size_t)n * sizeof(int));   // -1

    int blocks = (n + TPB * APT - 1) / (TPB * APT);
    k1_assign<<<blocks, TPB>>>(anc, gts, n, m, out, (unsigned long long*)ptop);
    k2_claims<<<1, 256>>>((const unsigned long long*)ptop, m, (int*)pforced);
    k3_merge<<<(n + 255) / 256, 256>>>((const int*)pforced, n, out);
}